// round 4
// baseline (speedup 1.0000x reference)
#include <cuda_runtime.h>

#define Bb 64
#define Cc 256
#define Hh 64
#define Ww 64
#define Ss (Hh*Ww)   // 4096
#define HID 16

// scratch (no allocations allowed) — zero-initialized, self-resetting
__device__ float g_z[Bb*Ss];            // channel-contracted logits pre-pool
__device__ float g_attn[Bb*Ss];         // softmax attention
__device__ float g_y[Bb*Cc];            // attention-pooled features
__device__ float g_gate[Bb*Cc];         // SE gate
__device__ unsigned int g_cnt[Bb];      // phase-1 arrival counters
__device__ unsigned int g_flag[Bb];     // gate-ready flags
__device__ unsigned int g_cnt2[Bb];     // consumption counters

// ---------------------------------------------------------------------------
// K1: z[b][s] = sum_c x[b][c][s] * conv_w[c]
// grid = Bb * 8 = 512 blocks, 128 threads, one float4 per thread
// ---------------------------------------------------------------------------
__global__ void k1_channel_dot(const float* __restrict__ x,
                               const float* __restrict__ conv_w) {
    __shared__ float wsh[Cc];
    if (threadIdx.x < 128) {
        wsh[threadIdx.x] = conv_w[threadIdx.x];
        wsh[threadIdx.x + 128] = conv_w[threadIdx.x + 128];
    }
    __syncthreads();

    int blk = blockIdx.x;
    int b = blk >> 3;
    int s4 = ((blk & 7) << 7) + threadIdx.x;
    const float4* x4 = reinterpret_cast<const float4*>(x + (size_t)b * Cc * Ss) + s4;

    float4 acc = make_float4(0.f, 0.f, 0.f, 0.f);
#pragma unroll 8
    for (int c = 0; c < Cc; c++) {
        float w = wsh[c];
        float4 v = x4[(size_t)c * (Ss / 4)];
        acc.x = fmaf(v.x, w, acc.x);
        acc.y = fmaf(v.y, w, acc.y);
        acc.z = fmaf(v.z, w, acc.z);
        acc.w = fmaf(v.w, w, acc.w);
    }
    reinterpret_cast<float4*>(g_z + (size_t)b * Ss)[s4] = acc;
}

// ---------------------------------------------------------------------------
// K2: 3x3x3 avg pool (t in group-of-8, h, w; zero pad; /27) + bias + softmax
// one block per batch (64 blocks, 256 threads)
// ---------------------------------------------------------------------------
__global__ void k2_pool_softmax(const float* __restrict__ conv_b) {
    __shared__ float zs[Ss];
    __shared__ float red[32];

    int b = blockIdx.x;
    int g = b >> 3;
    int t = b & 7;
    int tlo = (t > 0) ? t - 1 : 0;
    int thi = (t < 7) ? t + 1 : 7;

    {
        float4* zs4 = reinterpret_cast<float4*>(zs);
#pragma unroll
        for (int i = threadIdx.x; i < Ss / 4; i += 256) {
            float4 v = make_float4(0.f, 0.f, 0.f, 0.f);
            for (int tt = tlo; tt <= thi; tt++) {
                float4 u = reinterpret_cast<const float4*>(g_z + (g * 8 + tt) * Ss)[i];
                v.x += u.x; v.y += u.y; v.z += u.z; v.w += u.w;
            }
            zs4[i] = v;
        }
    }
    __syncthreads();

    const float cb = conv_b[0];
    float lg[16];
    float lmax = -1e30f;
#pragma unroll
    for (int i = 0; i < 16; i++) {
        int s = threadIdx.x + (i << 8);
        int h = s >> 6, w = s & 63;
        float sum = 0.f;
#pragma unroll
        for (int dh = -1; dh <= 1; dh++) {
            int hh = h + dh;
            if (hh < 0 || hh >= Hh) continue;
#pragma unroll
            for (int dw = -1; dw <= 1; dw++) {
                int ww = w + dw;
                if (ww < 0 || ww >= Ww) continue;
                sum += zs[(hh << 6) + ww];
            }
        }
        float l = sum * (1.f / 27.f) + cb;
        lg[i] = l;
        lmax = fmaxf(lmax, l);
    }

    for (int o = 16; o; o >>= 1) lmax = fmaxf(lmax, __shfl_xor_sync(0xffffffffu, lmax, o));
    if ((threadIdx.x & 31) == 0) red[threadIdx.x >> 5] = lmax;
    __syncthreads();
    if (threadIdx.x < 32) {
        float v = (threadIdx.x < 8) ? red[threadIdx.x] : -1e30f;
        for (int o = 4; o; o >>= 1) v = fmaxf(v, __shfl_xor_sync(0xffffffffu, v, o));
        if (threadIdx.x == 0) red[0] = v;
    }
    __syncthreads();
    lmax = red[0];
    __syncthreads();

    float lsum = 0.f;
#pragma unroll
    for (int i = 0; i < 16; i++) {
        lg[i] = expf(lg[i] - lmax);
        lsum += lg[i];
    }
    for (int o = 16; o; o >>= 1) lsum += __shfl_xor_sync(0xffffffffu, lsum, o);
    if ((threadIdx.x & 31) == 0) red[threadIdx.x >> 5] = lsum;
    __syncthreads();
    if (threadIdx.x < 32) {
        float v = (threadIdx.x < 8) ? red[threadIdx.x] : 0.f;
        for (int o = 4; o; o >>= 1) v += __shfl_xor_sync(0xffffffffu, v, o);
        if (threadIdx.x == 0) red[0] = v;
    }
    __syncthreads();
    float inv = 1.f / red[0];
#pragma unroll
    for (int i = 0; i < 16; i++) {
        int s = threadIdx.x + (i << 8);
        g_attn[b * Ss + s] = lg[i] * inv;
    }
}

// ---------------------------------------------------------------------------
// K35: fused weighted-pool + SE MLP + scale. One block per (b,c); x row
// (32 floats/thread) stays in REGISTERS across the per-batch gate wait, so
// x is read from DRAM exactly once here instead of twice.
// grid = Bb*Cc = 16384 blocks, 128 threads
// ---------------------------------------------------------------------------
__global__ void __launch_bounds__(128) k35_fused(const float* __restrict__ x,
                                                 const float* __restrict__ fc1,
                                                 const float* __restrict__ fc2,
                                                 float* __restrict__ out) {
    int bc = blockIdx.x;
    int b = bc >> 8;                       // Cc = 256
    int tid = threadIdx.x;
    const float4* x4 = reinterpret_cast<const float4*>(x + (size_t)bc * Ss);
    const float4* a4 = reinterpret_cast<const float4*>(g_attn + (size_t)b * Ss);

    // phase 1: load row into registers, dot with attn
    float4 rx[8];
    float acc = 0.f;
#pragma unroll
    for (int i = 0; i < 8; i++) {
        float4 v = x4[tid + (i << 7)];
        float4 a = a4[tid + (i << 7)];
        rx[i] = v;
        acc += v.x * a.x + v.y * a.y + v.z * a.z + v.w * a.w;
    }
    for (int o = 16; o; o >>= 1) acc += __shfl_xor_sync(0xffffffffu, acc, o);
    __shared__ float red[4];
    __shared__ unsigned int s_old;
    __shared__ float s_gate;
    if ((tid & 31) == 0) red[tid >> 5] = acc;
    __syncthreads();
    if (tid == 0) {
        g_y[bc] = red[0] + red[1] + red[2] + red[3];
        __threadfence();
        s_old = atomicAdd(&g_cnt[b], 1u);
    }
    __syncthreads();

    // phase 2: last-arriving block of this batch runs the SE MLP
    if (s_old == Cc - 1) {
        __shared__ float ys[Cc];
        __shared__ float hs[HID];
        ys[tid]       = __ldcg(&g_y[b * Cc + tid]);
        ys[tid + 128] = __ldcg(&g_y[b * Cc + tid + 128]);
        __syncthreads();

        int warp = tid >> 5, lane = tid & 31;     // 4 warps x 4 hid units each
#pragma unroll
        for (int u = 0; u < 4; u++) {
            int h = (warp << 2) + u;
            float a = 0.f;
#pragma unroll
            for (int i = 0; i < Cc / 32; i++) {
                int c = lane + (i << 5);
                a = fmaf(ys[c], fc1[h * Cc + c], a);
            }
            for (int o = 16; o; o >>= 1) a += __shfl_xor_sync(0xffffffffu, a, o);
            if (lane == 0) hs[h] = fmaxf(a, 0.f);
        }
        __syncthreads();
#pragma unroll
        for (int r = 0; r < 2; r++) {
            int c = tid + (r << 7);
            float a = 0.f;
            const float* w2 = fc2 + c * HID;
#pragma unroll
            for (int j = 0; j < HID; j++) a = fmaf(hs[j], w2[j], a);
            g_gate[b * Cc + c] = 1.f / (1.f + expf(-a));
        }
        __syncthreads();
        if (tid == 0) {
            __threadfence();
            atomicExch(&g_flag[b], 1u);
        }
    }

    // phase 3: wait for gate, then scale the register-resident row
    if (tid == 0) {
        unsigned int f = __ldcg(&g_flag[b]);
        while (!f) {
            __nanosleep(64);
            f = __ldcg(&g_flag[b]);
        }
        __threadfence();            // order gate load after flag observation
        s_gate = __ldcg(&g_gate[bc]);
    }
    __syncthreads();
    float gv = s_gate;

    float4* o4 = reinterpret_cast<float4*>(out + (size_t)bc * Ss);
#pragma unroll
    for (int i = 0; i < 8; i++) {
        float4 v = rx[i];
        v.x *= gv; v.y *= gv; v.z *= gv; v.w *= gv;
        o4[tid + (i << 7)] = v;
    }

    // cleanup: last consumer resets the batch's counters for the next replay
    if (tid == 0) {
        unsigned int old2 = atomicAdd(&g_cnt2[b], 1u);
        if (old2 == Cc - 1) {
            g_cnt[b] = 0;
            g_cnt2[b] = 0;
            g_flag[b] = 0;
        }
    }
}

// ---------------------------------------------------------------------------
extern "C" void kernel_launch(void* const* d_in, const int* in_sizes, int n_in,
                              void* d_out, int out_size) {
    const float* x      = (const float*)d_in[0];
    const float* conv_w = (const float*)d_in[1];
    const float* conv_b = (const float*)d_in[2];
    const float* fc1_w  = (const float*)d_in[3];
    const float* fc2_w  = (const float*)d_in[4];
    float* out = (float*)d_out;

    k1_channel_dot<<<Bb * 8, 128>>>(x, conv_w);
    k2_pool_softmax<<<Bb, 256>>>(conv_b);
    k35_fused<<<Bb * Cc, 128>>>(x, fc1_w, fc2_w, out);
}

// round 5
// speedup vs baseline: 1.1975x; 1.1975x over previous
#include <cuda_runtime.h>

#define Bb 64
#define Cc 256
#define Hh 64
#define Ww 64
#define Ss (Hh*Ww)   // 4096
#define HID 16
#define CSPLIT 4     // channel split for k1

// scratch (no allocations allowed) — zero-initialized, self-resetting
__device__ float g_zp[CSPLIT][Bb*Ss];   // partial channel-contracted logits
__device__ float g_attn[Bb*Ss];         // softmax attention
__device__ float g_y[Bb*Cc];            // attention-pooled features
__device__ float g_gate[Bb*Cc];         // SE gate
__device__ unsigned int g_cnt[Bb];      // per-batch completion counters

// ---------------------------------------------------------------------------
// K1: zp[p][b][s] = sum_{c in chunk p} x[b][c][s] * conv_w[c]
// grid = Bb * 8 * CSPLIT = 2048 blocks, 128 threads, one float4 per thread
// ---------------------------------------------------------------------------
__global__ void k1_channel_dot(const float* __restrict__ x,
                               const float* __restrict__ conv_w) {
    int blk = blockIdx.x;
    int p = blk & (CSPLIT - 1);                 // channel chunk
    int sc = (blk >> 2) & 7;                    // spatial chunk
    int b = blk >> 5;                           // batch
    int c0 = p * (Cc / CSPLIT);

    __shared__ float wsh[Cc / CSPLIT];
    if (threadIdx.x < Cc / CSPLIT)
        wsh[threadIdx.x] = conv_w[c0 + threadIdx.x];
    __syncthreads();

    int s4 = (sc << 7) + threadIdx.x;           // float4 index in [0,1024)
    const float4* x4 = reinterpret_cast<const float4*>(
        x + (size_t)b * Cc * Ss + (size_t)c0 * Ss) + s4;

    float4 acc = make_float4(0.f, 0.f, 0.f, 0.f);
#pragma unroll 8
    for (int c = 0; c < Cc / CSPLIT; c++) {
        float w = wsh[c];
        float4 v = x4[(size_t)c * (Ss / 4)];
        acc.x = fmaf(v.x, w, acc.x);
        acc.y = fmaf(v.y, w, acc.y);
        acc.z = fmaf(v.z, w, acc.z);
        acc.w = fmaf(v.w, w, acc.w);
    }
    reinterpret_cast<float4*>(g_zp[p] + (size_t)b * Ss)[s4] = acc;
}

// ---------------------------------------------------------------------------
// K2: sum partials + 3x3x3 avg pool (zero pad, /27) + bias + softmax
// one block per batch (64 blocks, 256 threads)
// ---------------------------------------------------------------------------
__global__ void k2_pool_softmax(const float* __restrict__ conv_b) {
    __shared__ float zs[Ss];
    __shared__ float red[32];

    int b = blockIdx.x;
    int g = b >> 3;
    int t = b & 7;
    int tlo = (t > 0) ? t - 1 : 0;
    int thi = (t < 7) ? t + 1 : 7;

    {
        float4* zs4 = reinterpret_cast<float4*>(zs);
#pragma unroll
        for (int i = threadIdx.x; i < Ss / 4; i += 256) {
            float4 v = make_float4(0.f, 0.f, 0.f, 0.f);
            for (int tt = tlo; tt <= thi; tt++) {
#pragma unroll
                for (int p = 0; p < CSPLIT; p++) {
                    float4 u = reinterpret_cast<const float4*>(
                        g_zp[p] + (g * 8 + tt) * Ss)[i];
                    v.x += u.x; v.y += u.y; v.z += u.z; v.w += u.w;
                }
            }
            zs4[i] = v;
        }
    }
    __syncthreads();

    const float cb = conv_b[0];
    float lg[16];
    float lmax = -1e30f;
#pragma unroll
    for (int i = 0; i < 16; i++) {
        int s = threadIdx.x + (i << 8);
        int h = s >> 6, w = s & 63;
        float sum = 0.f;
#pragma unroll
        for (int dh = -1; dh <= 1; dh++) {
            int hh = h + dh;
            if (hh < 0 || hh >= Hh) continue;
#pragma unroll
            for (int dw = -1; dw <= 1; dw++) {
                int ww = w + dw;
                if (ww < 0 || ww >= Ww) continue;
                sum += zs[(hh << 6) + ww];
            }
        }
        float l = sum * (1.f / 27.f) + cb;
        lg[i] = l;
        lmax = fmaxf(lmax, l);
    }

    for (int o = 16; o; o >>= 1) lmax = fmaxf(lmax, __shfl_xor_sync(0xffffffffu, lmax, o));
    if ((threadIdx.x & 31) == 0) red[threadIdx.x >> 5] = lmax;
    __syncthreads();
    if (threadIdx.x < 32) {
        float v = (threadIdx.x < 8) ? red[threadIdx.x] : -1e30f;
        for (int o = 4; o; o >>= 1) v = fmaxf(v, __shfl_xor_sync(0xffffffffu, v, o));
        if (threadIdx.x == 0) red[0] = v;
    }
    __syncthreads();
    lmax = red[0];
    __syncthreads();

    float lsum = 0.f;
#pragma unroll
    for (int i = 0; i < 16; i++) {
        lg[i] = expf(lg[i] - lmax);
        lsum += lg[i];
    }
    for (int o = 16; o; o >>= 1) lsum += __shfl_xor_sync(0xffffffffu, lsum, o);
    if ((threadIdx.x & 31) == 0) red[threadIdx.x >> 5] = lsum;
    __syncthreads();
    if (threadIdx.x < 32) {
        float v = (threadIdx.x < 8) ? red[threadIdx.x] : 0.f;
        for (int o = 4; o; o >>= 1) v += __shfl_xor_sync(0xffffffffu, v, o);
        if (threadIdx.x == 0) red[0] = v;
    }
    __syncthreads();
    float inv = 1.f / red[0];
#pragma unroll
    for (int i = 0; i < 16; i++) {
        int s = threadIdx.x + (i << 8);
        g_attn[b * Ss + s] = lg[i] * inv;
    }
}

// ---------------------------------------------------------------------------
// K3: y[b][c] = sum_s x[b][c][s] * attn[b][s]  (forward order)
// Fused tail: last-finishing block of each batch runs the SE MLP (no one waits).
// grid = Bb*Cc = 16384 blocks, 128 threads
// ---------------------------------------------------------------------------
__global__ void k3_weighted_pool_mlp(const float* __restrict__ x,
                                     const float* __restrict__ fc1,
                                     const float* __restrict__ fc2) {
    int bc = blockIdx.x;
    int b = bc >> 8;                          // Cc = 256
    const float4* x4 = reinterpret_cast<const float4*>(x + (size_t)bc * Ss);
    const float4* a4 = reinterpret_cast<const float4*>(g_attn + (size_t)b * Ss);

    float acc = 0.f;
#pragma unroll
    for (int i = threadIdx.x; i < Ss / 4; i += 128) {
        float4 v = x4[i];
        float4 a = a4[i];
        acc += v.x * a.x + v.y * a.y + v.z * a.z + v.w * a.w;
    }
    for (int o = 16; o; o >>= 1) acc += __shfl_xor_sync(0xffffffffu, acc, o);
    __shared__ float red[4];
    __shared__ unsigned int s_old;
    if ((threadIdx.x & 31) == 0) red[threadIdx.x >> 5] = acc;
    __syncthreads();
    if (threadIdx.x == 0) {
        g_y[bc] = red[0] + red[1] + red[2] + red[3];
        __threadfence();
        s_old = atomicAdd(&g_cnt[b], 1u);
    }
    __syncthreads();

    if (s_old == Cc - 1) {
        // last block of batch b: run the SE MLP
        __shared__ float ys[Cc];
        __shared__ float hs[HID];
        int tid = threadIdx.x;
        ys[tid]       = __ldcg(&g_y[b * Cc + tid]);
        ys[tid + 128] = __ldcg(&g_y[b * Cc + tid + 128]);
        __syncthreads();

        int warp = tid >> 5, lane = tid & 31;     // 4 warps x 4 hid units each
#pragma unroll
        for (int u = 0; u < 4; u++) {
            int h = (warp << 2) + u;
            float a = 0.f;
#pragma unroll
            for (int i = 0; i < Cc / 32; i++) {
                int c = lane + (i << 5);
                a = fmaf(ys[c], fc1[h * Cc + c], a);
            }
            for (int o = 16; o; o >>= 1) a += __shfl_xor_sync(0xffffffffu, a, o);
            if (lane == 0) hs[h] = fmaxf(a, 0.f);
        }
        __syncthreads();
#pragma unroll
        for (int r = 0; r < 2; r++) {
            int c = tid + (r << 7);
            float a = 0.f;
            const float* w2 = fc2 + c * HID;
#pragma unroll
            for (int j = 0; j < HID; j++) a = fmaf(hs[j], w2[j], a);
            g_gate[b * Cc + c] = 1.f / (1.f + expf(-a));
        }
        if (tid == 0) g_cnt[b] = 0;   // reset for next graph replay
    }
}

// ---------------------------------------------------------------------------
// K5: out = x * gate[b,c]   (float4, one per thread)
// grid = 65536 blocks, 256 threads
// ---------------------------------------------------------------------------
__global__ void k5_scale(const float* __restrict__ x, float* __restrict__ out) {
    size_t i4 = (size_t)blockIdx.x * blockDim.x + threadIdx.x;
    float gv = g_gate[i4 >> 10];          // Ss/4 = 1024 float4 per (b,c)
    float4 v = reinterpret_cast<const float4*>(x)[i4];
    v.x *= gv; v.y *= gv; v.z *= gv; v.w *= gv;
    reinterpret_cast<float4*>(out)[i4] = v;
}

// ---------------------------------------------------------------------------
extern "C" void kernel_launch(void* const* d_in, const int* in_sizes, int n_in,
                              void* d_out, int out_size) {
    const float* x      = (const float*)d_in[0];
    const float* conv_w = (const float*)d_in[1];
    const float* conv_b = (const float*)d_in[2];
    const float* fc1_w  = (const float*)d_in[3];
    const float* fc2_w  = (const float*)d_in[4];
    float* out = (float*)d_out;

    k1_channel_dot<<<Bb * 8 * CSPLIT, 128>>>(x, conv_w);
    k2_pool_softmax<<<Bb, 256>>>(conv_b);
    k3_weighted_pool_mlp<<<Bb * Cc, 128>>>(x, fc1_w, fc2_w);
    k5_scale<<<(size_t)Bb * Cc * Ss / 4 / 256, 256>>>(x, out);
}